// round 1
// baseline (speedup 1.0000x reference)
#include <cuda_runtime.h>
#include <cstdint>

// ---------------------------------------------------------------------------
// CFModule_12575664243188:
//   x: [B=16, H=256, W=256, C=64] fp32
//   pooled = adaptive_avg_pool 4x4  -> [B,16,64]
//   dots[b,i,j] = 0.25 * sum_n pooled[b,n,i]*pooled[b,n,j]; attn = softmax_j
//   out[b,h,w,t] = gelu_erf( sum_c x[b,h,w,c] * attn[b,t,c] )
// ---------------------------------------------------------------------------

#define B_    16
#define Hc    256
#define Wc    256
#define Cc    64
#define HW    (Hc*Wc)          // 65536
#define TILE_S 128

__device__ float g_pooled[B_ * 16 * Cc];   // mean-pooled, [b][n][c]
__device__ float g_attn[B_ * Cc * Cc];     // attn, [b][t][c]

// packed fp32x2 FMA (Blackwell FFMA2, PTX-only)
#define FMA2(acc, xv, av) \
    asm("fma.rn.f32x2 %0, %1, %2, %0;" : "+l"(acc) : "l"(xv), "l"(av))

// ---------------------------------------------------------------------------
// Kernel A: 4x4 adaptive average pool. grid = B*16 blocks, 256 threads.
// Each block reduces one 64x64 spatial window over all 64 channels (1 MB read).
// ---------------------------------------------------------------------------
__global__ void __launch_bounds__(256) pool_kernel(const float* __restrict__ x)
{
    int blk = blockIdx.x;            // b*16 + n
    int b = blk >> 4;
    int n = blk & 15;
    int ph = n >> 2, pw = n & 3;
    int tid = threadIdx.x;

    float4 acc = make_float4(0.f, 0.f, 0.f, 0.f);
    for (int h = 0; h < 64; ++h) {
        const float4* row = (const float4*)(
            x + (((size_t)b * Hc + (size_t)ph * 64 + h) * Wc + (size_t)pw * 64) * Cc);
        #pragma unroll
        for (int it = 0; it < 4; ++it) {
            float4 v = row[tid + 256 * it];
            acc.x += v.x; acc.y += v.y; acc.z += v.z; acc.w += v.w;
        }
    }
    // thread's float4 index within a row satisfies f % 16 == tid % 16,
    // so c-group = tid % 16 is constant for the whole accumulation.
    __shared__ float4 sm[256];
    sm[tid] = acc;
    __syncthreads();
    if (tid < 64) {
        int c = tid;
        int r = c >> 2;      // float4 group within the 16-group row pattern
        int j = c & 3;
        float s = 0.f;
        #pragma unroll
        for (int q = 0; q < 16; ++q)
            s += ((const float*)&sm[r + 16 * q])[j];
        g_pooled[(b * 16 + n) * Cc + c] = s * (1.0f / 4096.0f);
    }
}

// ---------------------------------------------------------------------------
// Kernel B: channel-channel gram + softmax. grid = B blocks, 64 threads.
// ---------------------------------------------------------------------------
__global__ void __launch_bounds__(64) attn_kernel()
{
    int b = blockIdx.x;
    int i = threadIdx.x;          // channel row
    __shared__ float xs[64][17];  // [channel][n], padded
    float my[16];
    #pragma unroll
    for (int n = 0; n < 16; ++n) {
        float v = g_pooled[(b * 16 + n) * Cc + i];
        xs[i][n] = v;
        my[n] = v;
    }
    __syncthreads();

    float d[64];
    float mx = -1e30f;
    #pragma unroll
    for (int j = 0; j < 64; ++j) {
        float s = 0.f;
        #pragma unroll
        for (int n = 0; n < 16; ++n) s += my[n] * xs[j][n];
        s *= 0.25f;               // n^-0.5 = 16^-0.5
        d[j] = s;
        mx = fmaxf(mx, s);
    }
    float sum = 0.f;
    #pragma unroll
    for (int j = 0; j < 64; ++j) { d[j] = expf(d[j] - mx); sum += d[j]; }
    float inv = 1.0f / sum;
    #pragma unroll
    for (int j = 0; j < 64; ++j)
        g_attn[((size_t)b * Cc + i) * Cc + j] = d[j] * inv;
}

// ---------------------------------------------------------------------------
// Kernel C: out[s,t] = gelu( sum_c x[s,c] * attn[t,c] ), per batch.
// grid = (HW/TILE_S, B), 256 threads.
// Thread layout: t = tid & 63 (output channel), group = tid >> 6 (0..3),
// each group (2 warps) handles 32 spatial rows of the 128-row tile.
// attn row pre-packed in 32 f32x2 registers; x-row reads are warp-broadcast.
// ---------------------------------------------------------------------------
__global__ void __launch_bounds__(256) gemm_gelu_kernel(const float* __restrict__ x,
                                                        float* __restrict__ out)
{
    __shared__ float xs[TILE_S][Cc];

    int b   = blockIdx.y;
    int s0  = blockIdx.x * TILE_S;
    int tid = threadIdx.x;
    int t   = tid & 63;
    int grp = tid >> 6;

    // attn row -> 32 packed f32x2 registers
    unsigned long long a2[32];
    const unsigned long long* arow =
        (const unsigned long long*)(g_attn + ((size_t)b * Cc + t) * Cc);
    #pragma unroll
    for (int i = 0; i < 32; ++i) a2[i] = arow[i];

    // load x tile [TILE_S x 64] to smem (coalesced float4)
    const float4* gx = (const float4*)(x + ((size_t)b * HW + s0) * Cc);
    float4* sx = (float4*)xs;
    #pragma unroll
    for (int it = 0; it < 8; ++it)
        sx[tid + 256 * it] = gx[tid + 256 * it];
    __syncthreads();

    float* outbase = out + ((size_t)b * HW + s0) * Cc;

    #pragma unroll 2
    for (int s = grp * 32; s < grp * 32 + 32; ++s) {
        const unsigned long long* xr = (const unsigned long long*)xs[s];
        unsigned long long acc0 = 0ull, acc1 = 0ull, acc2 = 0ull, acc3 = 0ull;
        #pragma unroll
        for (int i = 0; i < 32; i += 4) {
            FMA2(acc0, xr[i + 0], a2[i + 0]);
            FMA2(acc1, xr[i + 1], a2[i + 1]);
            FMA2(acc2, xr[i + 2], a2[i + 2]);
            FMA2(acc3, xr[i + 3], a2[i + 3]);
        }
        float l0, h0, l1, h1, l2, h2, l3, h3;
        asm("mov.b64 {%0,%1}, %2;" : "=f"(l0), "=f"(h0) : "l"(acc0));
        asm("mov.b64 {%0,%1}, %2;" : "=f"(l1), "=f"(h1) : "l"(acc1));
        asm("mov.b64 {%0,%1}, %2;" : "=f"(l2), "=f"(h2) : "l"(acc2));
        asm("mov.b64 {%0,%1}, %2;" : "=f"(l3), "=f"(h3) : "l"(acc3));
        float v = ((l0 + h0) + (l1 + h1)) + ((l2 + h2) + (l3 + h3));
        // exact-erf GELU (matches torch nn.GELU default)
        float g = 0.5f * v * (1.0f + erff(v * 0.70710678118654752f));
        outbase[(size_t)s * Cc + t] = g;
    }
}

extern "C" void kernel_launch(void* const* d_in, const int* in_sizes, int n_in,
                              void* d_out, int out_size)
{
    const float* x = (const float*)d_in[0];
    float* out = (float*)d_out;
    (void)in_sizes; (void)n_in; (void)out_size;

    pool_kernel<<<B_ * 16, 256>>>(x);
    attn_kernel<<<B_, 64>>>();
    gemm_gelu_kernel<<<dim3(HW / TILE_S, B_), 256>>>(x, out);
}

// round 3
// speedup vs baseline: 3.2309x; 3.2309x over previous
#include <cuda_runtime.h>
#include <cuda_bf16.h>
#include <cstdint>

// ---------------------------------------------------------------------------
// CFModule_12575664243188 on sm_103a (compute_103-safe: no tcgen05):
//   x: [B=16, H=256, W=256, C=64] fp32
//   pooled = adaptive_avg_pool 4x4  -> [B,16,64]
//   dots[b,i,j] = 0.25 * <pooled[:,i], pooled[:,j]>; attn = softmax_j
//   out[b,s,t] = gelu_erf( sum_c x[b,s,c] * attn[b,t,c] )
//
// Main GEMM: mma.sync m16n8k16 bf16 with 2-term split precision (hi+lo),
// 3 accumulated MMA products -> ~1e-5 relative error, fp32 accumulate.
// ---------------------------------------------------------------------------

#define B_    16
#define Hc    256
#define Wc    256
#define Cc    64
#define HW    (Hc*Wc)          // 65536
#define TILE_S 128

// --------------------------- global scratch --------------------------------
__device__ float g_pp[1024 * 64];                    // pool partials [b][n][q][c]
__device__ uint4 g_attn_h4[B_ * 64 * 64 * 2 / 16];   // attn hi bf16 [b][t][c]
__device__ uint4 g_attn_l4[B_ * 64 * 64 * 2 / 16];   // attn lo bf16

// --------------------------- helpers ---------------------------------------
__device__ __forceinline__ uint32_t smem_u32(const void* p) {
    uint32_t a;
    asm("{ .reg .u64 t; cvta.to.shared.u64 t, %1; cvt.u32.u64 %0, t; }"
        : "=r"(a) : "l"(p));
    return a;
}

__device__ __forceinline__ void ldsm_x4(uint32_t& r0, uint32_t& r1,
                                        uint32_t& r2, uint32_t& r3, uint32_t addr) {
    asm volatile("ldmatrix.sync.aligned.m8n8.x4.shared.b16 {%0,%1,%2,%3}, [%4];"
                 : "=r"(r0), "=r"(r1), "=r"(r2), "=r"(r3) : "r"(addr));
}

__device__ __forceinline__ void mma_bf16(float* c, uint32_t a0, uint32_t a1,
                                         uint32_t a2, uint32_t a3,
                                         uint32_t b0, uint32_t b1) {
    asm volatile(
        "mma.sync.aligned.m16n8k16.row.col.f32.bf16.bf16.f32 "
        "{%0,%1,%2,%3}, {%4,%5,%6,%7}, {%8,%9}, {%0,%1,%2,%3};"
        : "+f"(c[0]), "+f"(c[1]), "+f"(c[2]), "+f"(c[3])
        : "r"(a0), "r"(a1), "r"(a2), "r"(a3), "r"(b0), "r"(b1));
}

// pack two fp32 -> bf16x2 (first arg -> low 16 bits)
__device__ __forceinline__ uint32_t pack_bf(float lo_val, float hi_val) {
    uint32_t r;
    asm("cvt.rn.bf16x2.f32 %0, %1, %2;" : "=r"(r) : "f"(hi_val), "f"(lo_val));
    return r;
}

__device__ __forceinline__ float gelu_erf(float v) {
    return 0.5f * v * (1.0f + erff(v * 0.70710678118654752f));
}

// ---------------------------------------------------------------------------
// Kernel A: pool partials. grid = 1024 (b*64 + n*4 + q), 256 threads.
// Each block sums 16 h-rows of one 64x64 window over 64 channels.
// ---------------------------------------------------------------------------
__global__ void __launch_bounds__(256) pool_kernel(const float* __restrict__ x)
{
    int blk = blockIdx.x;
    int q = blk & 3, n = (blk >> 2) & 15, b = blk >> 6;
    int ph = n >> 2, pw = n & 3;
    int tid = threadIdx.x;

    float4 acc = make_float4(0.f, 0.f, 0.f, 0.f);
    for (int hh = 0; hh < 16; ++hh) {
        int h = ph * 64 + q * 16 + hh;
        const float4* row = (const float4*)(
            x + (((size_t)b * Hc + h) * Wc + (size_t)pw * 64) * Cc);
        #pragma unroll
        for (int it = 0; it < 4; ++it) {
            float4 v = row[tid + 256 * it];
            acc.x += v.x; acc.y += v.y; acc.z += v.z; acc.w += v.w;
        }
    }
    __shared__ float4 sm[256];
    sm[tid] = acc;
    __syncthreads();
    if (tid < 64) {
        int r = tid >> 2, j = tid & 3;
        float s = 0.f;
        #pragma unroll
        for (int w = 0; w < 16; ++w)
            s += ((const float*)&sm[r + 16 * w])[j];
        g_pp[blk * 64 + tid] = s;
    }
}

// ---------------------------------------------------------------------------
// Kernel B: merge partials, gram + softmax, emit bf16 hi/lo attn.
// grid = B blocks, 64 threads (thread i = attn row i).
// ---------------------------------------------------------------------------
__global__ void __launch_bounds__(64) attn_kernel()
{
    int b = blockIdx.x;
    int i = threadIdx.x;
    __shared__ float xs[64][17];
    float my[16];
    #pragma unroll
    for (int n = 0; n < 16; ++n) {
        int base = ((b * 16 + n) * 4) * 64 + i;
        float v = (g_pp[base] + g_pp[base + 64] + g_pp[base + 128] + g_pp[base + 192])
                  * (1.0f / 4096.0f);
        xs[i][n] = v;
        my[n] = v;
    }
    __syncthreads();

    float d[64];
    float mx = -1e30f;
    #pragma unroll
    for (int j = 0; j < 64; ++j) {
        float s = 0.f;
        #pragma unroll
        for (int n = 0; n < 16; ++n) s += my[n] * xs[j][n];
        s *= 0.25f;
        d[j] = s;
        mx = fmaxf(mx, s);
    }
    float sum = 0.f;
    #pragma unroll
    for (int j = 0; j < 64; ++j) { d[j] = expf(d[j] - mx); sum += d[j]; }
    float inv = 1.0f / sum;

    __nv_bfloat16* ah = (__nv_bfloat16*)g_attn_h4;
    __nv_bfloat16* al = (__nv_bfloat16*)g_attn_l4;
    size_t rb = ((size_t)b * 64 + i) * 64;
    #pragma unroll
    for (int j = 0; j < 64; ++j) {
        float a = d[j] * inv;
        __nv_bfloat16 h = __float2bfloat16(a);
        float hv = __bfloat162float(h);
        ah[rb + j] = h;
        al[rb + j] = __float2bfloat16(a - hv);
    }
}

// ---------------------------------------------------------------------------
// Kernel C: mma.sync bf16 GEMM + exact-erf GELU.
// grid = (HW/128, B), 256 threads (8 warps). D[128x64] = X[128x64] * Attn^T.
// Warp w owns M-rows [w*16, w*16+16). Split: D = Xh*Ah + Xl*Ah + Xh*Al.
//
// SMEM layout (static, exactly 48KB):
//   XH [128][64] bf16 (16KB), XL (16KB), BH [64][64] bf16 (8KB), BL (8KB)
// All tiles: 128B rows with 16B-granular XOR swizzle:
//   off(row, kbyte) = row*128 + (kbyte ^ ((row&7)<<4))
// ---------------------------------------------------------------------------
#define OFF_XH 0
#define OFF_XL 16384
#define OFF_BH 32768
#define OFF_BL 40960

__global__ void __launch_bounds__(256) gemm_kernel(const float* __restrict__ x,
                                                   float* __restrict__ out)
{
    __shared__ __align__(128) unsigned char smem[49152];
    uint32_t sb = smem_u32(smem);
    int tid = threadIdx.x;
    int wid = tid >> 5, lid = tid & 31;
    int b = blockIdx.y;
    int s0 = blockIdx.x * TILE_S;

    // ---- x tile [128x64] fp32 -> bf16 hi/lo, swizzled smem
    const float4* gx = (const float4*)(x + ((size_t)b * HW + s0) * Cc);
    #pragma unroll
    for (int it = 0; it < 8; ++it) {
        int f = tid + 256 * it;               // float4 index (2048 total)
        float4 v = gx[f];
        uint32_t p0 = pack_bf(v.x, v.y);
        uint32_t p1 = pack_bf(v.z, v.w);
        float hx = __uint_as_float(p0 << 16);
        float hy = __uint_as_float(p0 & 0xFFFF0000u);
        float hz = __uint_as_float(p1 << 16);
        float hw = __uint_as_float(p1 & 0xFFFF0000u);
        uint32_t q0 = pack_bf(v.x - hx, v.y - hy);
        uint32_t q1 = pack_bf(v.z - hz, v.w - hw);
        int row = f >> 4;
        uint32_t kbyte = (f & 15) * 8;
        uint32_t off = row * 128 + (kbyte ^ ((row & 7) << 4));
        *(uint2*)(smem + OFF_XH + off) = make_uint2(p0, p1);
        *(uint2*)(smem + OFF_XL + off) = make_uint2(q0, q1);
    }

    // ---- attn tile [64x64] bf16 hi/lo, swizzled smem
    const uint4* gh = g_attn_h4 + (size_t)b * 256;
    const uint4* gl = g_attn_l4 + (size_t)b * 256;
    #pragma unroll
    for (int it = 0; it < 2; ++it) {
        int m = tid + 256 * it;               // uint4 index (512 total)
        int row = m >> 3;
        uint32_t kbyte = (m & 7) * 16;
        uint32_t off = row * 128 + (kbyte ^ ((row & 7) << 4));
        *(uint4*)(smem + OFF_BH + off) = gh[m];
        *(uint4*)(smem + OFF_BL + off) = gl[m];
    }
    __syncthreads();

    // ---- MMA mainloop
    float acc[8][4];
    #pragma unroll
    for (int i = 0; i < 8; ++i)
        #pragma unroll
        for (int j = 0; j < 4; ++j) acc[i][j] = 0.f;

    // A ldmatrix lane address components
    uint32_t a_row = wid * 16 + (lid & 15);
    uint32_t a_k16 = (lid >> 4) & 1;          // 0/1 -> +16B (k 8..15)
    // B ldmatrix lane address components (x4 = two n-tiles per load)
    uint32_t b_nrow_lo = (lid & 7) + ((lid >> 4) & 1) * 8;  // within 16-row pair
    uint32_t b_k16 = (lid >> 3) & 1;

    #pragma unroll
    for (int kc = 0; kc < 4; ++kc) {
        uint32_t kb = kc * 32;
        uint32_t akb = kb + a_k16 * 16;
        uint32_t a_off = a_row * 128 + (akb ^ ((a_row & 7) << 4));
        uint32_t ah0, ah1, ah2, ah3, al0, al1, al2, al3;
        ldsm_x4(ah0, ah1, ah2, ah3, sb + OFF_XH + a_off);
        ldsm_x4(al0, al1, al2, al3, sb + OFF_XL + a_off);

        #pragma unroll
        for (int ntp = 0; ntp < 4; ++ntp) {
            uint32_t bn = ntp * 16 + b_nrow_lo;
            uint32_t bkb = kb + b_k16 * 16;
            uint32_t b_off = bn * 128 + (bkb ^ ((bn & 7) << 4));
            uint32_t bh0, bh1, bh2, bh3, bl0, bl1, bl2, bl3;
            ldsm_x4(bh0, bh1, bh2, bh3, sb + OFF_BH + b_off);
            ldsm_x4(bl0, bl1, bl2, bl3, sb + OFF_BL + b_off);

            float* c0 = acc[ntp * 2];
            float* c1 = acc[ntp * 2 + 1];
            mma_bf16(c0, ah0, ah1, ah2, ah3, bh0, bh1);
            mma_bf16(c0, al0, al1, al2, al3, bh0, bh1);
            mma_bf16(c0, ah0, ah1, ah2, ah3, bl0, bl1);
            mma_bf16(c1, ah0, ah1, ah2, ah3, bh2, bh3);
            mma_bf16(c1, al0, al1, al2, al3, bh2, bh3);
            mma_bf16(c1, ah0, ah1, ah2, ah3, bl2, bl3);
        }
    }

    // ---- epilogue: GELU + store. Fragment: lane l -> rows (l>>2, l>>2+8),
    // cols nt*8 + (l&3)*2 (+1).
    float* ob = out + ((size_t)b * HW + s0) * Cc;
    int r0 = wid * 16 + (lid >> 2);
    int cbase = (lid & 3) * 2;
    #pragma unroll
    for (int nt = 0; nt < 8; ++nt) {
        int col = nt * 8 + cbase;
        float2 v0, v1;
        v0.x = gelu_erf(acc[nt][0]);
        v0.y = gelu_erf(acc[nt][1]);
        v1.x = gelu_erf(acc[nt][2]);
        v1.y = gelu_erf(acc[nt][3]);
        *(float2*)(ob + (size_t)r0 * Cc + col) = v0;
        *(float2*)(ob + (size_t)(r0 + 8) * Cc + col) = v1;
    }
}

// ---------------------------------------------------------------------------
extern "C" void kernel_launch(void* const* d_in, const int* in_sizes, int n_in,
                              void* d_out, int out_size)
{
    const float* x = (const float*)d_in[0];
    float* out = (float*)d_out;
    (void)in_sizes; (void)n_in; (void)out_size;

    pool_kernel<<<1024, 256>>>(x);
    attn_kernel<<<B_, 64>>>();
    gemm_kernel<<<dim3(HW / TILE_S, B_), 256>>>(x, out);
}